// round 5
// baseline (speedup 1.0000x reference)
#include <cuda_runtime.h>
#include <math.h>

#define FF      20
#define ED      16
#define VOCAB   50000
#define VTOT    (FF * VOCAB)       /* 1,000,000 */
#define NPAIR   190                /* FF*(FF-1)/2 */
#define NT      384                /* 2*NPAIR = 380 active, 12 warps */

__global__ __launch_bounds__(NT)
void ffm_kernel(const int* __restrict__ x,
                const float* __restrict__ Wl,
                const float* __restrict__ Wc,
                const float* __restrict__ bias,
                float* __restrict__ out)
{
    __shared__ float red[NT / 32];

    const int b = blockIdx.x;
    const int t = threadIdx.x;

    // ---- decode ordered pair: thread 2k ↔ (i,j), thread 2k+1 ↔ (j,i) ----
    int k = t >> 1;
    const bool active = (k < NPAIR);
    if (!active) k = NPAIR - 1;            // clamp: lanes 380..383 duplicate last pair
    int i = 0, kk = k;
    #pragma unroll 1
    while (kk >= FF - 1 - i) { kk -= FF - 1 - i; ++i; }
    int j = i + 1 + kk;
    if (t & 1) { int tmp = i; i = j; j = tmp; }    // ordered (p,q) = (i,j)

    // xo for field i of this row (x row is 80B -> L1/L2 hot after first lane)
    const int xoi = __ldg(x + b * FF + i) + i * VOCAB;

    // ---- gather my vector: V = Wc[j, xo_i, :]  (64B, 4x LDG.128, independent) ----
    const float4* src = reinterpret_cast<const float4*>(
        Wc + ((size_t)j * VTOT + (size_t)xoi) * ED);
    float4 v0 = __ldg(src + 0);
    float4 v1 = __ldg(src + 1);
    float4 v2 = __ldg(src + 2);
    float4 v3 = __ldg(src + 3);

    // linear term: threads 0..19 gather Wl[xo_f] (independent load)
    float lin = 0.0f;
    if (t < FF) {
        const int xot = __ldg(x + b * FF + t) + t * VOCAB;
        lin = __ldg(Wl + xot);
    }

    // ---- exchange with partner lane (lane ^ 1) and dot ----
    // partner of (i,j) holds Wc[i, xo_j]; both orderings computed -> x0.5
    float s = 0.0f;
    #define DOT4(v)                                                        \
        {                                                                  \
            s = fmaf((v).x, __shfl_xor_sync(0xffffffffu, (v).x, 1), s);    \
            s = fmaf((v).y, __shfl_xor_sync(0xffffffffu, (v).y, 1), s);    \
            s = fmaf((v).z, __shfl_xor_sync(0xffffffffu, (v).z, 1), s);    \
            s = fmaf((v).w, __shfl_xor_sync(0xffffffffu, (v).w, 1), s);    \
        }
    DOT4(v0); DOT4(v1); DOT4(v2); DOT4(v3);
    #undef DOT4

    float partial = (active ? 0.5f * s : 0.0f) + lin;

    // ---- block reduction (warp shfl + 12-slot smem) ----
    #pragma unroll
    for (int o = 16; o > 0; o >>= 1)
        partial += __shfl_down_sync(0xffffffffu, partial, o);
    if ((t & 31) == 0) red[t >> 5] = partial;
    __syncthreads();

    if (t == 0) {
        float z = bias[0];
        #pragma unroll
        for (int w = 0; w < NT / 32; w++) z += red[w];
        out[b] = 1.0f / (1.0f + expf(-z));
    }
}

extern "C" void kernel_launch(void* const* d_in, const int* in_sizes, int n_in,
                              void* d_out, int out_size)
{
    const int*   x    = (const int*)  d_in[0];   // (4096, 20) int32
    const float* Wl   = (const float*)d_in[1];   // (1e6, 1)  f32
    const float* Wc   = (const float*)d_in[2];   // (20, 1e6, 16) f32
    const float* bias = (const float*)d_in[3];   // (1,) f32
    float*       out  = (float*)d_out;           // (4096,) f32

    ffm_kernel<<<out_size, NT>>>(x, Wl, Wc, bias, out);
}